// round 1
// baseline (speedup 1.0000x reference)
#include <cuda_runtime.h>
#include <math.h>

// Problem constants (fixed by the reference)
#define B_   32
#define T_   2048
#define DIN  512
#define H_   512
#define M_   (B_ * T_)      // 65536 rows

// Scratch for gate z and candidate h_tilde (128 MB each) — __device__ globals,
// no runtime allocation.
__device__ float g_z [(size_t)M_ * H_];
__device__ float g_ht[(size_t)M_ * H_];

// ---------------- GEMM tile config ----------------
#define BM 128
#define BN 128
#define BK 16
#define TM 8
#define TN 8
// 256 threads: 16x16 thread grid, each computes 8x8

__global__ __launch_bounds__(256)
void gemm_fused(const float* __restrict__ x,
                const float* __restrict__ motion_mag,
                const float* __restrict__ Wz, const float* __restrict__ bz,
                const float* __restrict__ Wh, const float* __restrict__ bh,
                const float* __restrict__ p_mw, const float* __restrict__ p_mb,
                const float* __restrict__ p_alpha)
{
    const int tid = threadIdx.x;
    const int tx  = tid & 15;    // column group (n)
    const int ty  = tid >> 4;    // row group (m)

    const int by  = blockIdx.x;          // M tile index
    const int nb  = blockIdx.y;          // 0..7 combined N (0..3 = Wz, 4..7 = Wh)
    const bool is_z = (nb < 4);
    const float* __restrict__ W = is_z ? Wz : Wh;
    const int n0 = (is_z ? nb : nb - 4) * BN;
    const int m0 = by * BM;

    __shared__ float As[2][BK][BM + 4];
    __shared__ float Bs[2][BK][BN + 4];

    // Per-thread global load coordinates: tile is 128 rows x 16 cols = 512 float4.
    // vec id v = tid and tid+256 ; row = v>>2 ; col = (v&3)*4
    const int ar0 = tid >> 2;          // 0..63
    const int ar1 = ar0 + 64;          // 64..127
    const int ac0 = (tid & 3) * 4;     // 0,4,8,12

    const float* xA = x + (size_t)m0 * DIN;
    const float* wB = W + (size_t)n0 * DIN;

    float acc[TM][TN];
#pragma unroll
    for (int i = 0; i < TM; ++i)
#pragma unroll
        for (int j = 0; j < TN; ++j) acc[i][j] = 0.f;

    // Prologue: load tile 0 into buffer 0
    {
        float4 a0 = *(const float4*)(xA + (size_t)ar0 * DIN + ac0);
        float4 a1 = *(const float4*)(xA + (size_t)ar1 * DIN + ac0);
        float4 b0 = *(const float4*)(wB + (size_t)ar0 * DIN + ac0);
        float4 b1 = *(const float4*)(wB + (size_t)ar1 * DIN + ac0);
        As[0][ac0 + 0][ar0] = a0.x; As[0][ac0 + 1][ar0] = a0.y;
        As[0][ac0 + 2][ar0] = a0.z; As[0][ac0 + 3][ar0] = a0.w;
        As[0][ac0 + 0][ar1] = a1.x; As[0][ac0 + 1][ar1] = a1.y;
        As[0][ac0 + 2][ar1] = a1.z; As[0][ac0 + 3][ar1] = a1.w;
        Bs[0][ac0 + 0][ar0] = b0.x; Bs[0][ac0 + 1][ar0] = b0.y;
        Bs[0][ac0 + 2][ar0] = b0.z; Bs[0][ac0 + 3][ar0] = b0.w;
        Bs[0][ac0 + 0][ar1] = b1.x; Bs[0][ac0 + 1][ar1] = b1.y;
        Bs[0][ac0 + 2][ar1] = b1.z; Bs[0][ac0 + 3][ar1] = b1.w;
    }
    __syncthreads();

    const int NT = DIN / BK;   // 32 k-tiles

    for (int kt = 0; kt < NT; ++kt) {
        const int cur = kt & 1;
        float4 a0n, a1n, b0n, b1n;
        const bool have_next = (kt + 1 < NT);
        if (have_next) {
            const int k1 = (kt + 1) * BK;
            a0n = *(const float4*)(xA + (size_t)ar0 * DIN + k1 + ac0);
            a1n = *(const float4*)(xA + (size_t)ar1 * DIN + k1 + ac0);
            b0n = *(const float4*)(wB + (size_t)ar0 * DIN + k1 + ac0);
            b1n = *(const float4*)(wB + (size_t)ar1 * DIN + k1 + ac0);
        }

        // Compute current tile
#pragma unroll
        for (int kk = 0; kk < BK; ++kk) {
            float4 av0 = *(const float4*)&As[cur][kk][ty * TM + 0];
            float4 av1 = *(const float4*)&As[cur][kk][ty * TM + 4];
            float4 bv0 = *(const float4*)&Bs[cur][kk][tx * TN + 0];
            float4 bv1 = *(const float4*)&Bs[cur][kk][tx * TN + 4];
            float a[TM] = {av0.x, av0.y, av0.z, av0.w, av1.x, av1.y, av1.z, av1.w};
            float b[TN] = {bv0.x, bv0.y, bv0.z, bv0.w, bv1.x, bv1.y, bv1.z, bv1.w};
#pragma unroll
            for (int i = 0; i < TM; ++i)
#pragma unroll
                for (int j = 0; j < TN; ++j)
                    acc[i][j] = fmaf(a[i], b[j], acc[i][j]);
        }

        if (have_next) {
            const int nxt = cur ^ 1;
            As[nxt][ac0 + 0][ar0] = a0n.x; As[nxt][ac0 + 1][ar0] = a0n.y;
            As[nxt][ac0 + 2][ar0] = a0n.z; As[nxt][ac0 + 3][ar0] = a0n.w;
            As[nxt][ac0 + 0][ar1] = a1n.x; As[nxt][ac0 + 1][ar1] = a1n.y;
            As[nxt][ac0 + 2][ar1] = a1n.z; As[nxt][ac0 + 3][ar1] = a1n.w;
            Bs[nxt][ac0 + 0][ar0] = b0n.x; Bs[nxt][ac0 + 1][ar0] = b0n.y;
            Bs[nxt][ac0 + 2][ar0] = b0n.z; Bs[nxt][ac0 + 3][ar0] = b0n.w;
            Bs[nxt][ac0 + 0][ar1] = b1n.x; Bs[nxt][ac0 + 1][ar1] = b1n.y;
            Bs[nxt][ac0 + 2][ar1] = b1n.z; Bs[nxt][ac0 + 3][ar1] = b1n.w;
            __syncthreads();
        }
    }

    // ---------------- Epilogue ----------------
    const int mrow = m0 + ty * TM;
    const int ncol = n0 + tx * TN;

    if (is_z) {
        const float alpha = *p_alpha;
        const float a_sp  = log1pf(expf(alpha));          // softplus(alpha)
        const float mwv   = *p_mw;
        const float mbv   = *p_mb;
        float4 bzv0 = *(const float4*)(bz + ncol + 0);
        float4 bzv1 = *(const float4*)(bz + ncol + 4);
        const float bzv[TN] = {bzv0.x, bzv0.y, bzv0.z, bzv0.w,
                               bzv1.x, bzv1.y, bzv1.z, bzv1.w};
#pragma unroll
        for (int i = 0; i < TM; ++i) {
            const int m = mrow + i;
            const float mmv = motion_mag[m];
            const float sg  = 1.f / (1.f + expf(-(mwv * mmv + mbv)));
            const float tau = 1.f + a_sp * sg;
            const float inv_tau = 1.f / tau;
            float zrow[TN];
#pragma unroll
            for (int j = 0; j < TN; ++j) {
                const float pre = (acc[i][j] + bzv[j]) * inv_tau;
                zrow[j] = 1.f / (1.f + expf(-pre));
            }
            float* dst = g_z + (size_t)m * H_ + ncol;
            *(float4*)(dst + 0) = make_float4(zrow[0], zrow[1], zrow[2], zrow[3]);
            *(float4*)(dst + 4) = make_float4(zrow[4], zrow[5], zrow[6], zrow[7]);
        }
    } else {
        float4 bhv0 = *(const float4*)(bh + ncol + 0);
        float4 bhv1 = *(const float4*)(bh + ncol + 4);
        const float bhv[TN] = {bhv0.x, bhv0.y, bhv0.z, bhv0.w,
                               bhv1.x, bhv1.y, bhv1.z, bhv1.w};
#pragma unroll
        for (int i = 0; i < TM; ++i) {
            const int m = mrow + i;
            float hrow[TN];
#pragma unroll
            for (int j = 0; j < TN; ++j) hrow[j] = acc[i][j] + bhv[j];
            float* dst = g_ht + (size_t)m * H_ + ncol;
            *(float4*)(dst + 0) = make_float4(hrow[0], hrow[1], hrow[2], hrow[3]);
            *(float4*)(dst + 4) = make_float4(hrow[4], hrow[5], hrow[6], hrow[7]);
        }
    }
}

// ---------------- Sequential recurrence ----------------
// One thread per (b, h) chain: h_t = h_{t-1} + z_t * (htilde_t - h_{t-1}).
// Consecutive threads = consecutive h -> fully coalesced loads/stores.
__global__ __launch_bounds__(128)
void scan_kernel(float* __restrict__ out)
{
    const int tid = blockIdx.x * blockDim.x + threadIdx.x;  // 0..16383
    const int b = tid >> 9;            // / H_
    const int h = tid & (H_ - 1);

    const float* __restrict__ zp = g_z  + (size_t)b * T_ * H_ + h;
    const float* __restrict__ hp = g_ht + (size_t)b * T_ * H_ + h;
    float* __restrict__ op = out + (size_t)b * T_ * H_ + h;

    float hc = 0.f;
#pragma unroll 8
    for (int t = 0; t < T_; ++t) {
        const float zv = zp[(size_t)t * H_];
        const float hv = hp[(size_t)t * H_];
        hc = fmaf(zv, hv - hc, hc);
        op[(size_t)t * H_] = hc;
    }
}

extern "C" void kernel_launch(void* const* d_in, const int* in_sizes, int n_in,
                              void* d_out, int out_size)
{
    const float* x   = (const float*)d_in[0];
    const float* mm  = (const float*)d_in[1];
    const float* Wz  = (const float*)d_in[2];
    const float* bz  = (const float*)d_in[3];
    const float* Wh  = (const float*)d_in[4];
    const float* bh  = (const float*)d_in[5];
    const float* mw  = (const float*)d_in[6];
    const float* mb  = (const float*)d_in[7];
    const float* al  = (const float*)d_in[8];

    dim3 grid(M_ / BM, 8);       // 512 x 8 = 4096 blocks; y<4 -> Wz, y>=4 -> Wh
    gemm_fused<<<grid, 256>>>(x, mm, Wz, bz, Wh, bh, mw, mb, al);

    scan_kernel<<<(B_ * H_) / 128, 128>>>((float*)d_out);
}

// round 3
// speedup vs baseline: 1.8654x; 1.8654x over previous
#include <cuda_runtime.h>
#include <cuda_bf16.h>
#include <stdint.h>
#include <math.h>

// ---------------- Problem constants ----------------
#define B_SZ 32
#define T_SZ 2048
#define K_SZ 512
#define H_SZ 512
#define M_SZ (B_SZ * T_SZ)   // 65536

// ---------------- Static device scratch ----------------
__device__ __align__(256) __nv_bfloat16 g_Xhi[(size_t)M_SZ * K_SZ];   // 64 MB
__device__ __align__(256) __nv_bfloat16 g_Xlo[(size_t)M_SZ * K_SZ];   // 64 MB
__device__ __align__(256) __nv_bfloat16 g_Whi[(size_t)1024 * K_SZ];   // rows 0..511 Wz, 512..1023 Wh
__device__ __align__(256) __nv_bfloat16 g_Wlo[(size_t)1024 * K_SZ];
__device__ __align__(256) float g_z [(size_t)M_SZ * H_SZ];            // 128 MB
__device__ __align__(256) float g_ht[(size_t)M_SZ * H_SZ];            // 128 MB

// ---------------- helpers ----------------
__device__ __forceinline__ uint32_t smem_u32(const void* p) {
    uint32_t a;
    asm("{ .reg .u64 t; cvta.to.shared.u64 t, %1; cvt.u32.u64 %0, t; }" : "=r"(a) : "l"(p));
    return a;
}
__device__ __forceinline__ void cpa16(uint32_t s, const void* g) {
    asm volatile("cp.async.cg.shared.global [%0], [%1], 16;" :: "r"(s), "l"(g));
}
__device__ __forceinline__ uint32_t swz(uint32_t o) { return o ^ ((o >> 3) & 0x70); }

__device__ __forceinline__ void ldm_x4(uint32_t* r, uint32_t addr) {
    asm volatile("ldmatrix.sync.aligned.m8n8.x4.shared.b16 {%0,%1,%2,%3}, [%4];"
                 : "=r"(r[0]), "=r"(r[1]), "=r"(r[2]), "=r"(r[3]) : "r"(addr));
}
__device__ __forceinline__ void mma16816(float* d, const uint32_t* a, const uint32_t* b) {
    asm volatile(
        "mma.sync.aligned.m16n8k16.row.col.f32.bf16.bf16.f32 "
        "{%0,%1,%2,%3}, {%4,%5,%6,%7}, {%8,%9}, {%0,%1,%2,%3};"
        : "+f"(d[0]), "+f"(d[1]), "+f"(d[2]), "+f"(d[3])
        : "r"(a[0]), "r"(a[1]), "r"(a[2]), "r"(a[3]), "r"(b[0]), "r"(b[1]));
}
__device__ __forceinline__ float sigf(float x) { return 1.f / (1.f + expf(-x)); }

// ---------------- fp32 -> bf16 hi/lo split ----------------
__device__ __forceinline__ uint32_t pk2(__nv_bfloat16 a, __nv_bfloat16 b) {
    __nv_bfloat162 t = __halves2bfloat162(a, b);
    return *reinterpret_cast<uint32_t*>(&t);
}
__global__ __launch_bounds__(256) void conv_x_k(const float* __restrict__ x) {
    size_t i = (size_t)blockIdx.x * 256 + threadIdx.x;
    float4 v = reinterpret_cast<const float4*>(x)[i];
    __nv_bfloat16 h0 = __float2bfloat16(v.x), h1 = __float2bfloat16(v.y);
    __nv_bfloat16 h2 = __float2bfloat16(v.z), h3 = __float2bfloat16(v.w);
    __nv_bfloat16 l0 = __float2bfloat16(v.x - __bfloat162float(h0));
    __nv_bfloat16 l1 = __float2bfloat16(v.y - __bfloat162float(h1));
    __nv_bfloat16 l2 = __float2bfloat16(v.z - __bfloat162float(h2));
    __nv_bfloat16 l3 = __float2bfloat16(v.w - __bfloat162float(h3));
    reinterpret_cast<uint2*>(g_Xhi)[i] = make_uint2(pk2(h0, h1), pk2(h2, h3));
    reinterpret_cast<uint2*>(g_Xlo)[i] = make_uint2(pk2(l0, l1), pk2(l2, l3));
}
__global__ __launch_bounds__(256) void conv_w_k(const float* __restrict__ Wz,
                                                const float* __restrict__ Wh) {
    size_t i = (size_t)blockIdx.x * 256 + threadIdx.x;
    size_t e = i * 4;
    int np = (int)(e >> 9), col = (int)(e & 511);
    const float* src = (np < 512) ? (Wz + (size_t)np * 512 + col)
                                  : (Wh + (size_t)(np - 512) * 512 + col);
    float4 v = *reinterpret_cast<const float4*>(src);
    __nv_bfloat16 h0 = __float2bfloat16(v.x), h1 = __float2bfloat16(v.y);
    __nv_bfloat16 h2 = __float2bfloat16(v.z), h3 = __float2bfloat16(v.w);
    __nv_bfloat16 l0 = __float2bfloat16(v.x - __bfloat162float(h0));
    __nv_bfloat16 l1 = __float2bfloat16(v.y - __bfloat162float(h1));
    __nv_bfloat16 l2 = __float2bfloat16(v.z - __bfloat162float(h2));
    __nv_bfloat16 l3 = __float2bfloat16(v.w - __bfloat162float(h3));
    reinterpret_cast<uint2*>(g_Whi)[i] = make_uint2(pk2(h0, h1), pk2(h2, h3));
    reinterpret_cast<uint2*>(g_Wlo)[i] = make_uint2(pk2(l0, l1), pk2(l2, l3));
}

// ---------------- HMMA GEMM (mma.sync bf16, 3-term split) ----------------
// grid 4096: bx>>3 = M tile (128 rows), bx&7 = nb (0..3 Wz tiles, 4..7 Wh tiles).
// 256 threads = 8 warps: wm = w>>2 (2 row-halves of 64), wn = w&3 (4 col-quarters of 32).
// K processed as 24 chunks of 64: chunk c -> term t=c>>3 (0:Ah*Bh 1:Ah*Bl 2:Al*Bh), kc=c&7.
#define STAGE_B 32768   // A tile 16KB + B tile 16KB

__global__ __launch_bounds__(256, 2) void gemm_hmma(
    const float* __restrict__ mmag, const float* __restrict__ bz, const float* __restrict__ bh,
    const float* __restrict__ p_mw, const float* __restrict__ p_mb, const float* __restrict__ p_al)
{
    extern __shared__ char smem[];
    const uint32_t smb = smem_u32(smem);
    const int tid = threadIdx.x;
    const int w = tid >> 5, lane = tid & 31;
    const int wm = w >> 2, wn = w & 3;
    const int g = lane >> 2, tg = lane & 3;

    const int mt = blockIdx.x >> 3, nb = blockIdx.x & 7;
    const bool is_z = (nb < 4);
    const int m0 = mt * 128, n0 = (nb & 3) * 128;
    const int wrow0 = (is_z ? 0 : 512) + n0;   // row offset into combined W buffers

    // per-thread cp.async coordinates: 4 units for A, 4 for B; unit u: row=idx>>3, 16B-chunk=idx&7
    // per-thread ldmatrix lane geometry
    const int aRow = wm * 64 + (lane & 7) + ((lane >> 3) & 1) * 8;  // + mi*16
    const int aKb  = (lane >> 4) * 16;                              // + ks*32
    const int bRow = wn * 32 + (lane & 7) + (lane >> 4) * 8;        // + p*16
    const int bKb  = ((lane >> 3) & 1) * 16;                        // + ks*32

    float acc[4][4][4];
#pragma unroll
    for (int i = 0; i < 4; ++i)
#pragma unroll
        for (int j = 0; j < 4; ++j)
#pragma unroll
            for (int k = 0; k < 4; ++k) acc[i][j][k] = 0.f;

    auto load_chunk = [&](int c, int stage) {
        const int t = c >> 3, kc = c & 7;
        const __nv_bfloat16* aSrc = (t < 2 ? g_Xhi : g_Xlo) + (size_t)m0 * K_SZ + kc * 64;
        const __nv_bfloat16* bSrc = (t == 1 ? g_Wlo : g_Whi) + (size_t)wrow0 * K_SZ + kc * 64;
        const uint32_t sA = smb + stage * STAGE_B;
        const uint32_t sB = sA + 16384;
#pragma unroll
        for (int u = 0; u < 4; ++u) {
            const int idx = u * 256 + tid;
            const int row = idx >> 3, cc = idx & 7;
            cpa16(sA + swz((uint32_t)(row * 128 + cc * 16)), aSrc + (size_t)row * K_SZ + cc * 8);
        }
#pragma unroll
        for (int u = 0; u < 4; ++u) {
            const int idx = u * 256 + tid;
            const int row = idx >> 3, cc = idx & 7;
            cpa16(sB + swz((uint32_t)(row * 128 + cc * 16)), bSrc + (size_t)row * K_SZ + cc * 8);
        }
        asm volatile("cp.async.commit_group;");
    };

    load_chunk(0, 0);

#pragma unroll 1
    for (int c = 0; c < 24; ++c) {
        const int buf = c & 1;
        if (c + 1 < 24) {
            load_chunk(c + 1, buf ^ 1);
            asm volatile("cp.async.wait_group 1;");
        } else {
            asm volatile("cp.async.wait_group 0;");
        }
        __syncthreads();

        const uint32_t sA = smb + buf * STAGE_B;
        const uint32_t sB = sA + 16384;
#pragma unroll
        for (int ks = 0; ks < 4; ++ks) {
            uint32_t af[4][4], bf[4][2];
#pragma unroll
            for (int mi = 0; mi < 4; ++mi)
                ldm_x4(af[mi], sA + swz((uint32_t)((aRow + mi * 16) * 128 + aKb + ks * 32)));
#pragma unroll
            for (int p = 0; p < 2; ++p) {
                uint32_t r[4];
                ldm_x4(r, sB + swz((uint32_t)((bRow + p * 16) * 128 + bKb + ks * 32)));
                bf[p * 2 + 0][0] = r[0]; bf[p * 2 + 0][1] = r[1];
                bf[p * 2 + 1][0] = r[2]; bf[p * 2 + 1][1] = r[3];
            }
#pragma unroll
            for (int mi = 0; mi < 4; ++mi)
#pragma unroll
                for (int ni = 0; ni < 4; ++ni)
                    mma16816(acc[mi][ni], af[mi], bf[ni]);
        }
        __syncthreads();   // all warps done with buf before it is refilled
    }

    // ---------------- fused epilogue ----------------
    const int m0r = m0 + wm * 64;
    const int n0c = n0 + wn * 32;
    if (is_z) {
        const float a_sp = log1pf(expf(*p_al));
        const float mwv = *p_mw, mbv = *p_mb;
#pragma unroll
        for (int mi = 0; mi < 4; ++mi) {
            const int r0 = m0r + mi * 16 + g;
            const float it0 = 1.f / (1.f + a_sp * sigf(mwv * mmag[r0] + mbv));
            const float it1 = 1.f / (1.f + a_sp * sigf(mwv * mmag[r0 + 8] + mbv));
#pragma unroll
            for (int ni = 0; ni < 4; ++ni) {
                const int n = n0c + ni * 8 + tg * 2;
                const float2 bv = *reinterpret_cast<const float2*>(bz + n);
                const float* d = acc[mi][ni];
                float2 o0 = make_float2(sigf((d[0] + bv.x) * it0), sigf((d[1] + bv.y) * it0));
                float2 o1 = make_float2(sigf((d[2] + bv.x) * it1), sigf((d[3] + bv.y) * it1));
                *reinterpret_cast<float2*>(g_z + (size_t)r0 * H_SZ + n) = o0;
                *reinterpret_cast<float2*>(g_z + (size_t)(r0 + 8) * H_SZ + n) = o1;
            }
        }
    } else {
#pragma unroll
        for (int mi = 0; mi < 4; ++mi) {
            const int r0 = m0r + mi * 16 + g;
#pragma unroll
            for (int ni = 0; ni < 4; ++ni) {
                const int n = n0c + ni * 8 + tg * 2;
                const float2 bv = *reinterpret_cast<const float2*>(bh + n);
                const float* d = acc[mi][ni];
                float2 o0 = make_float2(d[0] + bv.x, d[1] + bv.y);
                float2 o1 = make_float2(d[2] + bv.x, d[3] + bv.y);
                *reinterpret_cast<float2*>(g_ht + (size_t)r0 * H_SZ + n) = o0;
                *reinterpret_cast<float2*>(g_ht + (size_t)(r0 + 8) * H_SZ + n) = o1;
            }
        }
    }
}

// ---------------- Sequential recurrence, batch-32 register staging ----------------
__global__ __launch_bounds__(64) void scan3(float* __restrict__ out)
{
    const int tid = blockIdx.x * 64 + threadIdx.x;   // 0..16383
    const int b = tid >> 9;
    const int h = tid & (H_SZ - 1);
    const float* __restrict__ zp = g_z  + (size_t)b * T_SZ * H_SZ + h;
    const float* __restrict__ hp = g_ht + (size_t)b * T_SZ * H_SZ + h;
    float* __restrict__ o = out + (size_t)b * T_SZ * H_SZ + h;

    float hc = 0.f;
#pragma unroll 1
    for (int t0 = 0; t0 < T_SZ; t0 += 32) {
        float zb[32], hb[32];
#pragma unroll
        for (int i = 0; i < 32; ++i) zb[i] = zp[(size_t)(t0 + i) * H_SZ];
#pragma unroll
        for (int i = 0; i < 32; ++i) hb[i] = hp[(size_t)(t0 + i) * H_SZ];
#pragma unroll
        for (int i = 0; i < 32; ++i) {
            hc = fmaf(zb[i], hb[i] - hc, hc);
            o[(size_t)(t0 + i) * H_SZ] = hc;
        }
    }
}

// ---------------- Launch ----------------
extern "C" void kernel_launch(void* const* d_in, const int* in_sizes, int n_in,
                              void* d_out, int out_size)
{
    const float* x  = (const float*)d_in[0];
    const float* mm = (const float*)d_in[1];
    const float* Wz = (const float*)d_in[2];
    const float* bz = (const float*)d_in[3];
    const float* Wh = (const float*)d_in[4];
    const float* bh = (const float*)d_in[5];
    const float* mw = (const float*)d_in[6];
    const float* mb = (const float*)d_in[7];
    const float* al = (const float*)d_in[8];

    static int smem_set = 0;
    if (!smem_set) {
        cudaFuncSetAttribute(gemm_hmma, cudaFuncAttributeMaxDynamicSharedMemorySize, 2 * STAGE_B);
        smem_set = 1;
    }

    conv_w_k<<<512, 256>>>(Wz, Wh);
    conv_x_k<<<32768, 256>>>(x);
    gemm_hmma<<<4096, 256, 2 * STAGE_B>>>(mm, bz, bh, mw, mb, al);
    scan3<<<256, 64>>>((float*)d_out);
}

// round 5
// speedup vs baseline: 2.3952x; 1.2840x over previous
#include <cuda_runtime.h>
#include <cuda_bf16.h>
#include <stdint.h>
#include <math.h>

// ---------------- Problem constants ----------------
#define B_SZ 32
#define T_SZ 2048
#define K_SZ 512
#define H_SZ 512
#define M_SZ (B_SZ * T_SZ)   // 65536
#define NCH  32              // scan chunks per chain
#define CHL  64              // chunk length (NCH*CHL = T_SZ)

// ---------------- Static device scratch ----------------
__device__ __align__(256) __nv_bfloat16 g_Xhi[(size_t)M_SZ * K_SZ];
__device__ __align__(256) __nv_bfloat16 g_Xlo[(size_t)M_SZ * K_SZ];
__device__ __align__(256) __nv_bfloat16 g_Whi[(size_t)1024 * K_SZ];
__device__ __align__(256) __nv_bfloat16 g_Wlo[(size_t)1024 * K_SZ];
__device__ __align__(256) float g_z [(size_t)M_SZ * H_SZ];
__device__ __align__(256) float g_ht[(size_t)M_SZ * H_SZ];
__device__ __align__(256) float g_A  [(size_t)B_SZ * NCH * H_SZ];  // 2 MB
__device__ __align__(256) float g_B  [(size_t)B_SZ * NCH * H_SZ];  // 2 MB
__device__ __align__(256) float g_hin[(size_t)B_SZ * NCH * H_SZ];  // 2 MB

// ---------------- helpers ----------------
__device__ __forceinline__ uint32_t smem_u32(const void* p) {
    uint32_t a;
    asm("{ .reg .u64 t; cvta.to.shared.u64 t, %1; cvt.u32.u64 %0, t; }" : "=r"(a) : "l"(p));
    return a;
}
__device__ __forceinline__ void cpa16(uint32_t s, const void* g) {
    asm volatile("cp.async.cg.shared.global [%0], [%1], 16;" :: "r"(s), "l"(g));
}
__device__ __forceinline__ uint32_t swz(uint32_t o) { return o ^ ((o >> 3) & 0x70); }
__device__ __forceinline__ void ldm_x4(uint32_t* r, uint32_t addr) {
    asm volatile("ldmatrix.sync.aligned.m8n8.x4.shared.b16 {%0,%1,%2,%3}, [%4];"
                 : "=r"(r[0]), "=r"(r[1]), "=r"(r[2]), "=r"(r[3]) : "r"(addr));
}
__device__ __forceinline__ void mma16816(float* d, const uint32_t* a, const uint32_t* b) {
    asm volatile(
        "mma.sync.aligned.m16n8k16.row.col.f32.bf16.bf16.f32 "
        "{%0,%1,%2,%3}, {%4,%5,%6,%7}, {%8,%9}, {%0,%1,%2,%3};"
        : "+f"(d[0]), "+f"(d[1]), "+f"(d[2]), "+f"(d[3])
        : "r"(a[0]), "r"(a[1]), "r"(a[2]), "r"(a[3]), "r"(b[0]), "r"(b[1]));
}
__device__ __forceinline__ float sigf(float x) { return 1.f / (1.f + expf(-x)); }
__device__ __forceinline__ uint32_t pk2(__nv_bfloat16 a, __nv_bfloat16 b) {
    __nv_bfloat162 t = __halves2bfloat162(a, b);
    return *reinterpret_cast<uint32_t*>(&t);
}

// ---------------- fp32 -> bf16 hi/lo split ----------------
__global__ __launch_bounds__(256) void conv_x_k(const float* __restrict__ x) {
    size_t i = (size_t)blockIdx.x * 256 + threadIdx.x;
    float4 v = reinterpret_cast<const float4*>(x)[i];
    __nv_bfloat16 h0 = __float2bfloat16(v.x), h1 = __float2bfloat16(v.y);
    __nv_bfloat16 h2 = __float2bfloat16(v.z), h3 = __float2bfloat16(v.w);
    __nv_bfloat16 l0 = __float2bfloat16(v.x - __bfloat162float(h0));
    __nv_bfloat16 l1 = __float2bfloat16(v.y - __bfloat162float(h1));
    __nv_bfloat16 l2 = __float2bfloat16(v.z - __bfloat162float(h2));
    __nv_bfloat16 l3 = __float2bfloat16(v.w - __bfloat162float(h3));
    reinterpret_cast<uint2*>(g_Xhi)[i] = make_uint2(pk2(h0, h1), pk2(h2, h3));
    reinterpret_cast<uint2*>(g_Xlo)[i] = make_uint2(pk2(l0, l1), pk2(l2, l3));
}
__global__ __launch_bounds__(256) void conv_w_k(const float* __restrict__ Wz,
                                                const float* __restrict__ Wh) {
    size_t i = (size_t)blockIdx.x * 256 + threadIdx.x;
    size_t e = i * 4;
    int np = (int)(e >> 9), col = (int)(e & 511);
    const float* src = (np < 512) ? (Wz + (size_t)np * 512 + col)
                                  : (Wh + (size_t)(np - 512) * 512 + col);
    float4 v = *reinterpret_cast<const float4*>(src);
    __nv_bfloat16 h0 = __float2bfloat16(v.x), h1 = __float2bfloat16(v.y);
    __nv_bfloat16 h2 = __float2bfloat16(v.z), h3 = __float2bfloat16(v.w);
    __nv_bfloat16 l0 = __float2bfloat16(v.x - __bfloat162float(h0));
    __nv_bfloat16 l1 = __float2bfloat16(v.y - __bfloat162float(h1));
    __nv_bfloat16 l2 = __float2bfloat16(v.z - __bfloat162float(h2));
    __nv_bfloat16 l3 = __float2bfloat16(v.w - __bfloat162float(h3));
    reinterpret_cast<uint2*>(g_Whi)[i] = make_uint2(pk2(h0, h1), pk2(h2, h3));
    reinterpret_cast<uint2*>(g_Wlo)[i] = make_uint2(pk2(l0, l1), pk2(l2, l3));
}

// ---------------- HMMA GEMM, 3-stage cp.async pipeline ----------------
#define STAGE_B 32768   // A tile 16KB + B tile 16KB
#define NSTAGE  3

__global__ __launch_bounds__(256, 2) void gemm_hmma(
    const float* __restrict__ mmag, const float* __restrict__ bz, const float* __restrict__ bh,
    const float* __restrict__ p_mw, const float* __restrict__ p_mb, const float* __restrict__ p_al)
{
    extern __shared__ char smem[];
    const uint32_t smb = smem_u32(smem);
    const int tid = threadIdx.x;
    const int w = tid >> 5, lane = tid & 31;
    const int wm = w >> 2, wn = w & 3;
    const int g = lane >> 2, tg = lane & 3;

    const int mt = blockIdx.x >> 3, nb = blockIdx.x & 7;
    const bool is_z = (nb < 4);
    const int m0 = mt * 128, n0 = (nb & 3) * 128;
    const int wrow0 = (is_z ? 0 : 512) + n0;

    const int aRow = wm * 64 + (lane & 7) + ((lane >> 3) & 1) * 8;
    const int aKb  = (lane >> 4) * 16;
    const int bRow = wn * 32 + (lane & 7) + (lane >> 4) * 8;
    const int bKb  = ((lane >> 3) & 1) * 16;

    float acc[4][4][4];
#pragma unroll
    for (int i = 0; i < 4; ++i)
#pragma unroll
        for (int j = 0; j < 4; ++j)
#pragma unroll
            for (int k = 0; k < 4; ++k) acc[i][j][k] = 0.f;

    auto load_chunk = [&](int c, int stage) {
        const int t = c >> 3, kc = c & 7;
        const __nv_bfloat16* aSrc = (t < 2 ? g_Xhi : g_Xlo) + (size_t)m0 * K_SZ + kc * 64;
        const __nv_bfloat16* bSrc = (t == 1 ? g_Wlo : g_Whi) + (size_t)wrow0 * K_SZ + kc * 64;
        const uint32_t sA = smb + stage * STAGE_B;
        const uint32_t sB = sA + 16384;
#pragma unroll
        for (int u = 0; u < 4; ++u) {
            const int idx = u * 256 + tid;
            const int row = idx >> 3, cc = idx & 7;
            cpa16(sA + swz((uint32_t)(row * 128 + cc * 16)), aSrc + (size_t)row * K_SZ + cc * 8);
        }
#pragma unroll
        for (int u = 0; u < 4; ++u) {
            const int idx = u * 256 + tid;
            const int row = idx >> 3, cc = idx & 7;
            cpa16(sB + swz((uint32_t)(row * 128 + cc * 16)), bSrc + (size_t)row * K_SZ + cc * 8);
        }
        asm volatile("cp.async.commit_group;");
    };

    load_chunk(0, 0);
    load_chunk(1, 1);

#pragma unroll 1
    for (int c = 0; c < 24; ++c) {
        if (c + 1 < 24) asm volatile("cp.async.wait_group 1;");
        else            asm volatile("cp.async.wait_group 0;");
        __syncthreads();            // chunk c resident; all warps done with stage (c+2)%3

        if (c + 2 < 24) load_chunk(c + 2, (c + 2) % NSTAGE);

        const uint32_t sA = smb + (c % NSTAGE) * STAGE_B;
        const uint32_t sB = sA + 16384;
#pragma unroll
        for (int ks = 0; ks < 4; ++ks) {
            uint32_t af[4][4], bf[4][2];
#pragma unroll
            for (int mi = 0; mi < 4; ++mi)
                ldm_x4(af[mi], sA + swz((uint32_t)((aRow + mi * 16) * 128 + aKb + ks * 32)));
#pragma unroll
            for (int p = 0; p < 2; ++p) {
                uint32_t r[4];
                ldm_x4(r, sB + swz((uint32_t)((bRow + p * 16) * 128 + bKb + ks * 32)));
                bf[p * 2 + 0][0] = r[0]; bf[p * 2 + 0][1] = r[1];
                bf[p * 2 + 1][0] = r[2]; bf[p * 2 + 1][1] = r[3];
            }
#pragma unroll
            for (int mi = 0; mi < 4; ++mi)
#pragma unroll
                for (int ni = 0; ni < 4; ++ni)
                    mma16816(acc[mi][ni], af[mi], bf[ni]);
        }
    }

    // ---------------- fused epilogue ----------------
    const int m0r = m0 + wm * 64;
    const int n0c = n0 + wn * 32;
    if (is_z) {
        const float a_sp = log1pf(expf(*p_al));
        const float mwv = *p_mw, mbv = *p_mb;
#pragma unroll
        for (int mi = 0; mi < 4; ++mi) {
            const int r0 = m0r + mi * 16 + g;
            const float it0 = 1.f / (1.f + a_sp * sigf(mwv * mmag[r0] + mbv));
            const float it1 = 1.f / (1.f + a_sp * sigf(mwv * mmag[r0 + 8] + mbv));
#pragma unroll
            for (int ni = 0; ni < 4; ++ni) {
                const int n = n0c + ni * 8 + tg * 2;
                const float2 bv = *reinterpret_cast<const float2*>(bz + n);
                const float* d = acc[mi][ni];
                float2 o0 = make_float2(sigf((d[0] + bv.x) * it0), sigf((d[1] + bv.y) * it0));
                float2 o1 = make_float2(sigf((d[2] + bv.x) * it1), sigf((d[3] + bv.y) * it1));
                *reinterpret_cast<float2*>(g_z + (size_t)r0 * H_SZ + n) = o0;
                *reinterpret_cast<float2*>(g_z + (size_t)(r0 + 8) * H_SZ + n) = o1;
            }
        }
    } else {
#pragma unroll
        for (int mi = 0; mi < 4; ++mi) {
            const int r0 = m0r + mi * 16 + g;
#pragma unroll
            for (int ni = 0; ni < 4; ++ni) {
                const int n = n0c + ni * 8 + tg * 2;
                const float2 bv = *reinterpret_cast<const float2*>(bh + n);
                const float* d = acc[mi][ni];
                float2 o0 = make_float2(d[0] + bv.x, d[1] + bv.y);
                float2 o1 = make_float2(d[2] + bv.x, d[3] + bv.y);
                *reinterpret_cast<float2*>(g_ht + (size_t)r0 * H_SZ + n) = o0;
                *reinterpret_cast<float2*>(g_ht + (size_t)(r0 + 8) * H_SZ + n) = o1;
            }
        }
    }
}

// ---------------- Chunked associative scan ----------------
// Recurrence h_t = (1-z_t)*h_{t-1} + z_t*ht_t is affine: h_out = A*h_in + B per chunk.
// P1: per-(b,chunk,h) affine aggregate.
__global__ __launch_bounds__(512) void scan_p1()
{
    const int h = threadIdx.x;          // 0..511
    const int c = blockIdx.x;           // 0..31
    const int b = blockIdx.y;           // 0..31
    const size_t base = ((size_t)b * T_SZ + (size_t)c * CHL) * H_SZ + h;
    const float* __restrict__ zp = g_z  + base;
    const float* __restrict__ hp = g_ht + base;

    float A = 1.f, Bv = 0.f;
#pragma unroll 4
    for (int t = 0; t < CHL; ++t) {
        const float zv = zp[(size_t)t * H_SZ];
        const float hv = hp[(size_t)t * H_SZ];
        Bv = fmaf(zv, hv - Bv, Bv);
        A *= (1.f - zv);
    }
    const size_t o = ((size_t)b * NCH + c) * H_SZ + h;
    g_A[o] = A;
    g_B[o] = Bv;
}

// P2: one warp per chain; lane = chunk. Inclusive shfl scan of affine maps,
// then shift down to get carry-in h for each chunk.
__global__ __launch_bounds__(256) void scan_p2()
{
    const int w = (blockIdx.x * 256 + threadIdx.x) >> 5;   // chain 0..16383
    const int lane = threadIdx.x & 31;                      // chunk index
    const int b = w >> 9, h = w & (H_SZ - 1);
    const size_t o = ((size_t)b * NCH + lane) * H_SZ + h;
    float A = g_A[o], Bv = g_B[o];
#pragma unroll
    for (int off = 1; off < 32; off <<= 1) {
        const float Ao = __shfl_up_sync(0xFFFFFFFFu, A, off);
        const float Bo = __shfl_up_sync(0xFFFFFFFFu, Bv, off);
        if (lane >= off) {
            Bv = fmaf(A, Bo, Bv);   // compose: this ∘ earlier (h_in = 0 chain start)
            A *= Ao;
        }
    }
    float hin = __shfl_up_sync(0xFFFFFFFFu, Bv, 1);
    if (lane == 0) hin = 0.f;
    g_hin[o] = hin;
}

// P3: replay each chunk from its carry-in, write final h.
__global__ __launch_bounds__(512) void scan_p3(float* __restrict__ out)
{
    const int h = threadIdx.x;
    const int c = blockIdx.x;
    const int b = blockIdx.y;
    const size_t base = ((size_t)b * T_SZ + (size_t)c * CHL) * H_SZ + h;
    const float* __restrict__ zp = g_z  + base;
    const float* __restrict__ hp = g_ht + base;
    float* __restrict__ op = out + base;

    float hc = g_hin[((size_t)b * NCH + c) * H_SZ + h];
#pragma unroll 4
    for (int t = 0; t < CHL; ++t) {
        const float zv = zp[(size_t)t * H_SZ];
        const float hv = hp[(size_t)t * H_SZ];
        hc = fmaf(zv, hv - hc, hc);
        op[(size_t)t * H_SZ] = hc;
    }
}

// ---------------- Launch ----------------
extern "C" void kernel_launch(void* const* d_in, const int* in_sizes, int n_in,
                              void* d_out, int out_size)
{
    const float* x  = (const float*)d_in[0];
    const float* mm = (const float*)d_in[1];
    const float* Wz = (const float*)d_in[2];
    const float* bz = (const float*)d_in[3];
    const float* Wh = (const float*)d_in[4];
    const float* bh = (const float*)d_in[5];
    const float* mw = (const float*)d_in[6];
    const float* mb = (const float*)d_in[7];
    const float* al = (const float*)d_in[8];

    static int smem_set = 0;
    if (!smem_set) {
        cudaFuncSetAttribute(gemm_hmma, cudaFuncAttributeMaxDynamicSharedMemorySize,
                             NSTAGE * STAGE_B);
        smem_set = 1;
    }

    conv_w_k<<<512, 256>>>(Wz, Wh);
    conv_x_k<<<32768, 256>>>(x);
    gemm_hmma<<<4096, 256, NSTAGE * STAGE_B>>>(mm, bz, bh, mw, mb, al);

    dim3 cg(NCH, B_SZ);
    scan_p1<<<cg, 512>>>();
    // 16384 chains * 32 lanes = 524288 threads / 256 = 2048 blocks
    scan_p2<<<2048, 256>>>();
    scan_p3<<<cg, 512>>>((float*)d_out);
}

// round 6
// speedup vs baseline: 2.4581x; 1.0263x over previous
#include <cuda_runtime.h>
#include <cuda_bf16.h>
#include <cuda_fp16.h>
#include <stdint.h>
#include <math.h>

// ---------------- Problem constants ----------------
#define B_SZ 32
#define T_SZ 2048
#define K_SZ 512
#define H_SZ 512
#define M_SZ (B_SZ * T_SZ)   // 65536
#define NCH  32              // scan chunks per chain
#define CHL  64              // chunk length

// ---------------- Static device scratch ----------------
__device__ __align__(256) __nv_bfloat16 g_Xhi[(size_t)M_SZ * K_SZ];   // 64 MB
__device__ __align__(256) __nv_bfloat16 g_Xlo[(size_t)M_SZ * K_SZ];   // 64 MB
__device__ __align__(256) __nv_bfloat16 g_Whi[(size_t)1024 * K_SZ];   // rows 0..511 Wz, 512..1023 Wh
__device__ __align__(256) __nv_bfloat16 g_Wlo[(size_t)1024 * K_SZ];
__device__ __align__(256) __half2 g_ab[(size_t)M_SZ * H_SZ];          // 128 MB (a=1-z, b=z*ht)
__device__ __align__(256) float g_A  [(size_t)B_SZ * NCH * H_SZ];     // 2 MB
__device__ __align__(256) float g_B  [(size_t)B_SZ * NCH * H_SZ];     // 2 MB
__device__ __align__(256) float g_hin[(size_t)B_SZ * NCH * H_SZ];     // 2 MB

// ---------------- helpers ----------------
__device__ __forceinline__ uint32_t smem_u32(const void* p) {
    uint32_t a;
    asm("{ .reg .u64 t; cvta.to.shared.u64 t, %1; cvt.u32.u64 %0, t; }" : "=r"(a) : "l"(p));
    return a;
}
__device__ __forceinline__ void cpa16(uint32_t s, const void* g) {
    asm volatile("cp.async.cg.shared.global [%0], [%1], 16;" :: "r"(s), "l"(g));
}
__device__ __forceinline__ uint32_t swz(uint32_t o) { return o ^ ((o >> 3) & 0x70); }
__device__ __forceinline__ void ldm_x4(uint32_t* r, uint32_t addr) {
    asm volatile("ldmatrix.sync.aligned.m8n8.x4.shared.b16 {%0,%1,%2,%3}, [%4];"
                 : "=r"(r[0]), "=r"(r[1]), "=r"(r[2]), "=r"(r[3]) : "r"(addr));
}
__device__ __forceinline__ void mma16816(float* d, const uint32_t* a, const uint32_t* b) {
    asm volatile(
        "mma.sync.aligned.m16n8k16.row.col.f32.bf16.bf16.f32 "
        "{%0,%1,%2,%3}, {%4,%5,%6,%7}, {%8,%9}, {%0,%1,%2,%3};"
        : "+f"(d[0]), "+f"(d[1]), "+f"(d[2]), "+f"(d[3])
        : "r"(a[0]), "r"(a[1]), "r"(a[2]), "r"(a[3]), "r"(b[0]), "r"(b[1]));
}
__device__ __forceinline__ float sigf(float x) { return 1.f / (1.f + expf(-x)); }
__device__ __forceinline__ uint32_t pk2(__nv_bfloat16 a, __nv_bfloat16 b) {
    __nv_bfloat162 t = __halves2bfloat162(a, b);
    return *reinterpret_cast<uint32_t*>(&t);
}

// ---------------- fp32 -> bf16 hi/lo split ----------------
__global__ __launch_bounds__(256) void conv_x_k(const float* __restrict__ x) {
    size_t i = (size_t)blockIdx.x * 256 + threadIdx.x;
    float4 v = reinterpret_cast<const float4*>(x)[i];
    __nv_bfloat16 h0 = __float2bfloat16(v.x), h1 = __float2bfloat16(v.y);
    __nv_bfloat16 h2 = __float2bfloat16(v.z), h3 = __float2bfloat16(v.w);
    __nv_bfloat16 l0 = __float2bfloat16(v.x - __bfloat162float(h0));
    __nv_bfloat16 l1 = __float2bfloat16(v.y - __bfloat162float(h1));
    __nv_bfloat16 l2 = __float2bfloat16(v.z - __bfloat162float(h2));
    __nv_bfloat16 l3 = __float2bfloat16(v.w - __bfloat162float(h3));
    reinterpret_cast<uint2*>(g_Xhi)[i] = make_uint2(pk2(h0, h1), pk2(h2, h3));
    reinterpret_cast<uint2*>(g_Xlo)[i] = make_uint2(pk2(l0, l1), pk2(l2, l3));
}
__global__ __launch_bounds__(256) void conv_w_k(const float* __restrict__ Wz,
                                                const float* __restrict__ Wh) {
    size_t i = (size_t)blockIdx.x * 256 + threadIdx.x;
    size_t e = i * 4;
    int np = (int)(e >> 9), col = (int)(e & 511);
    const float* src = (np < 512) ? (Wz + (size_t)np * 512 + col)
                                  : (Wh + (size_t)(np - 512) * 512 + col);
    float4 v = *reinterpret_cast<const float4*>(src);
    __nv_bfloat16 h0 = __float2bfloat16(v.x), h1 = __float2bfloat16(v.y);
    __nv_bfloat16 h2 = __float2bfloat16(v.z), h3 = __float2bfloat16(v.w);
    __nv_bfloat16 l0 = __float2bfloat16(v.x - __bfloat162float(h0));
    __nv_bfloat16 l1 = __float2bfloat16(v.y - __bfloat162float(h1));
    __nv_bfloat16 l2 = __float2bfloat16(v.z - __bfloat162float(h2));
    __nv_bfloat16 l3 = __float2bfloat16(v.w - __bfloat162float(h3));
    reinterpret_cast<uint2*>(g_Whi)[i] = make_uint2(pk2(h0, h1), pk2(h2, h3));
    reinterpret_cast<uint2*>(g_Wlo)[i] = make_uint2(pk2(l0, l1), pk2(l2, l3));
}

// ---------------- Merged HMMA GEMM: z AND h tiles in one CTA ----------------
// grid 2048: mt = bx>>2 (128 M rows), nt = bx&3 (128 N cols).
// Per kc (K chunk of 64): stage holds 6 tiles of 16KB:
//   [0]=Ahi [1]=Alo [2]=Whi_z [3]=Whi_h [4]=Wlo_z [5]=Wlo_h
// Terms: acc_z += Ahi*Whi_z + Ahi*Wlo_z + Alo*Whi_z   (same for h).
#define TILE_B  16384
#define STAGE_B (6 * TILE_B)   // 96 KB
#define NSTG    2

__global__ __launch_bounds__(256, 1) void gemm_hmma(
    const float* __restrict__ mmag, const float* __restrict__ bz, const float* __restrict__ bh,
    const float* __restrict__ p_mw, const float* __restrict__ p_mb, const float* __restrict__ p_al)
{
    extern __shared__ char smem[];
    const uint32_t smb = smem_u32(smem);
    const int tid = threadIdx.x;
    const int w = tid >> 5, lane = tid & 31;
    const int wm = w >> 2, wn = w & 3;
    const int g = lane >> 2, tg = lane & 3;

    const int mt = blockIdx.x >> 2, nt = blockIdx.x & 3;
    const int m0 = mt * 128, n0 = nt * 128;
    const int wr_z = n0, wr_h = 512 + n0;

    const int aRow = wm * 64 + (lane & 7) + ((lane >> 3) & 1) * 8;
    const int aKb  = (lane >> 4) * 16;
    const int bRow = wn * 32 + (lane & 7) + (lane >> 4) * 8;
    const int bKb  = ((lane >> 3) & 1) * 16;

    float acc_z[4][4][4], acc_h[4][4][4];
#pragma unroll
    for (int i = 0; i < 4; ++i)
#pragma unroll
        for (int j = 0; j < 4; ++j)
#pragma unroll
            for (int k = 0; k < 4; ++k) { acc_z[i][j][k] = 0.f; acc_h[i][j][k] = 0.f; }

    auto load_tile = [&](const __nv_bfloat16* __restrict__ src, uint32_t sbase) {
#pragma unroll
        for (int u = 0; u < 4; ++u) {
            const int idx = u * 256 + tid;
            const int row = idx >> 3, cc = idx & 7;
            cpa16(sbase + swz((uint32_t)(row * 128 + cc * 16)), src + (size_t)row * K_SZ + cc * 8);
        }
    };
    auto load_chunk = [&](int kc, int stage) {
        const uint32_t sb = smb + stage * STAGE_B;
        const size_t ko = (size_t)kc * 64;
        load_tile(g_Xhi + (size_t)m0 * K_SZ + ko,   sb + 0 * TILE_B);
        load_tile(g_Xlo + (size_t)m0 * K_SZ + ko,   sb + 1 * TILE_B);
        load_tile(g_Whi + (size_t)wr_z * K_SZ + ko, sb + 2 * TILE_B);
        load_tile(g_Whi + (size_t)wr_h * K_SZ + ko, sb + 3 * TILE_B);
        load_tile(g_Wlo + (size_t)wr_z * K_SZ + ko, sb + 4 * TILE_B);
        load_tile(g_Wlo + (size_t)wr_h * K_SZ + ko, sb + 5 * TILE_B);
        asm volatile("cp.async.commit_group;");
    };

    load_chunk(0, 0);

#pragma unroll 1
    for (int kc = 0; kc < 8; ++kc) {
        asm volatile("cp.async.wait_group 0;");
        __syncthreads();                       // stage kc resident; other buffer free
        if (kc + 1 < 8) load_chunk(kc + 1, (kc + 1) & 1);

        const uint32_t sb = smb + (kc & 1) * STAGE_B;
#pragma unroll
        for (int ks = 0; ks < 4; ++ks) {
            uint32_t af[4][4], bf[4][2];
            // A-hi fragments (reused for Whi and Wlo passes)
#pragma unroll
            for (int mi = 0; mi < 4; ++mi)
                ldm_x4(af[mi], sb + 0 * TILE_B + swz((uint32_t)((aRow + mi * 16) * 128 + aKb + ks * 32)));

            auto bpass = [&](int tile, float (*acc)[4][4]) {
#pragma unroll
                for (int p = 0; p < 2; ++p) {
                    uint32_t r[4];
                    ldm_x4(r, sb + tile * TILE_B + swz((uint32_t)((bRow + p * 16) * 128 + bKb + ks * 32)));
                    bf[p * 2 + 0][0] = r[0]; bf[p * 2 + 0][1] = r[1];
                    bf[p * 2 + 1][0] = r[2]; bf[p * 2 + 1][1] = r[3];
                }
#pragma unroll
                for (int mi = 0; mi < 4; ++mi)
#pragma unroll
                    for (int ni = 0; ni < 4; ++ni)
                        mma16816(acc[mi][ni], af[mi], bf[ni]);
            };
            bpass(2, acc_z);   // Ahi * Whi_z
            bpass(3, acc_h);   // Ahi * Whi_h
            bpass(4, acc_z);   // Ahi * Wlo_z
            bpass(5, acc_h);   // Ahi * Wlo_h
            // A-lo fragments
#pragma unroll
            for (int mi = 0; mi < 4; ++mi)
                ldm_x4(af[mi], sb + 1 * TILE_B + swz((uint32_t)((aRow + mi * 16) * 128 + aKb + ks * 32)));
            bpass(2, acc_z);   // Alo * Whi_z
            bpass(3, acc_h);   // Alo * Whi_h
        }
    }

    // ---------------- fused epilogue: a = 1-z, b = z*ht, store half2 ----------------
    const float a_sp = log1pf(expf(*p_al));
    const float mwv = *p_mw, mbv = *p_mb;
    const int m0r = m0 + wm * 64;
    const int n0c = n0 + wn * 32;
#pragma unroll
    for (int mi = 0; mi < 4; ++mi) {
        const int r0 = m0r + mi * 16 + g;
        const float it0 = 1.f / (1.f + a_sp * sigf(mwv * mmag[r0] + mbv));
        const float it1 = 1.f / (1.f + a_sp * sigf(mwv * mmag[r0 + 8] + mbv));
#pragma unroll
        for (int ni = 0; ni < 4; ++ni) {
            const int n = n0c + ni * 8 + tg * 2;
            const float2 bzv = *reinterpret_cast<const float2*>(bz + n);
            const float2 bhv = *reinterpret_cast<const float2*>(bh + n);
            const float* dz = acc_z[mi][ni];
            const float* dh = acc_h[mi][ni];
            const float z0 = sigf((dz[0] + bzv.x) * it0), h0 = dh[0] + bhv.x;
            const float z1 = sigf((dz[1] + bzv.y) * it0), h1 = dh[1] + bhv.y;
            const float z2 = sigf((dz[2] + bzv.x) * it1), h2 = dh[2] + bhv.x;
            const float z3 = sigf((dz[3] + bzv.y) * it1), h3 = dh[3] + bhv.y;
            __half2 c0 = __floats2half2_rn(1.f - z0, z0 * h0);
            __half2 c1 = __floats2half2_rn(1.f - z1, z1 * h1);
            __half2 c2 = __floats2half2_rn(1.f - z2, z2 * h2);
            __half2 c3 = __floats2half2_rn(1.f - z3, z3 * h3);
            *reinterpret_cast<uint2*>(g_ab + (size_t)r0 * H_SZ + n) =
                make_uint2(*reinterpret_cast<uint32_t*>(&c0), *reinterpret_cast<uint32_t*>(&c1));
            *reinterpret_cast<uint2*>(g_ab + (size_t)(r0 + 8) * H_SZ + n) =
                make_uint2(*reinterpret_cast<uint32_t*>(&c2), *reinterpret_cast<uint32_t*>(&c3));
        }
    }
}

// ---------------- Chunked associative scan on (a,b):  h' = a*h + b ----------------
__global__ __launch_bounds__(512) void scan_p1()
{
    const int h = threadIdx.x;
    const int c = blockIdx.x;
    const int b = blockIdx.y;
    const size_t base = ((size_t)b * T_SZ + (size_t)c * CHL) * H_SZ + h;
    const __half2* __restrict__ p = g_ab + base;

    float A = 1.f, Bv = 0.f;
#pragma unroll 4
    for (int t = 0; t < CHL; ++t) {
        const float2 f = __half22float2(p[(size_t)t * H_SZ]);
        Bv = fmaf(f.x, Bv, f.y);
        A *= f.x;
    }
    const size_t o = ((size_t)b * NCH + c) * H_SZ + h;
    g_A[o] = A;
    g_B[o] = Bv;
}

__global__ __launch_bounds__(256) void scan_p2()
{
    const int w = (blockIdx.x * 256 + threadIdx.x) >> 5;   // chain 0..16383
    const int lane = threadIdx.x & 31;                      // chunk index
    const int b = w >> 9, h = w & (H_SZ - 1);
    const size_t o = ((size_t)b * NCH + lane) * H_SZ + h;
    float A = g_A[o], Bv = g_B[o];
#pragma unroll
    for (int off = 1; off < 32; off <<= 1) {
        const float Ao = __shfl_up_sync(0xFFFFFFFFu, A, off);
        const float Bo = __shfl_up_sync(0xFFFFFFFFu, Bv, off);
        if (lane >= off) {
            Bv = fmaf(A, Bo, Bv);
            A *= Ao;
        }
    }
    float hin = __shfl_up_sync(0xFFFFFFFFu, Bv, 1);
    if (lane == 0) hin = 0.f;
    g_hin[o] = hin;
}

__global__ __launch_bounds__(512) void scan_p3(float* __restrict__ out)
{
    const int h = threadIdx.x;
    const int c = blockIdx.x;
    const int b = blockIdx.y;
    const size_t base = ((size_t)b * T_SZ + (size_t)c * CHL) * H_SZ + h;
    const __half2* __restrict__ p = g_ab + base;
    float* __restrict__ op = out + base;

    float hc = g_hin[((size_t)b * NCH + c) * H_SZ + h];
#pragma unroll 4
    for (int t = 0; t < CHL; ++t) {
        const float2 f = __half22float2(p[(size_t)t * H_SZ]);
        hc = fmaf(f.x, hc, f.y);
        op[(size_t)t * H_SZ] = hc;
    }
}

// ---------------- Launch ----------------
extern "C" void kernel_launch(void* const* d_in, const int* in_sizes, int n_in,
                              void* d_out, int out_size)
{
    const float* x  = (const float*)d_in[0];
    const float* mm = (const float*)d_in[1];
    const float* Wz = (const float*)d_in[2];
    const float* bz = (const float*)d_in[3];
    const float* Wh = (const float*)d_in[4];
    const float* bh = (const float*)d_in[5];
    const float* mw = (const float*)d_in[6];
    const float* mb = (const float*)d_in[7];
    const float* al = (const float*)d_in[8];

    static int smem_set = 0;
    if (!smem_set) {
        cudaFuncSetAttribute(gemm_hmma, cudaFuncAttributeMaxDynamicSharedMemorySize,
                             NSTG * STAGE_B);
        smem_set = 1;
    }

    conv_w_k<<<512, 256>>>(Wz, Wh);
    conv_x_k<<<32768, 256>>>(x);
    gemm_hmma<<<2048, 256, NSTG * STAGE_B>>>(mm, bz, bh, mw, mb, al);

    dim3 cg(NCH, B_SZ);
    scan_p1<<<cg, 512>>>();
    scan_p2<<<2048, 256>>>();
    scan_p3<<<cg, 512>>>((float*)d_out);
}